// round 1
// baseline (speedup 1.0000x reference)
#include <cuda_runtime.h>

#define NN    10000
#define NE    320000
#define HID   16
#define NL    7
#define KTOT  10000
#define KCHUNK 500

// -------- scratch (no allocations allowed) --------
__device__ float g_deg_out[NN];
__device__ float g_deg_in[NN];
__device__ float g_norm_src[NN];
__device__ float g_norm_dst[NN];
__device__ float g_h[NN * HID];    // layer1 (features@W1)*norm_src
__device__ float g_agg1[NN * HID];
__device__ float g_h2[NN * 8];     // layer2 pre-scatter, padded to 8
__device__ float g_agg2[NN * 8];
__device__ int   g_is64;

__device__ __forceinline__ int edge_at(const int* __restrict__ p, int e, int is64) {
    return is64 ? p[2 * e] : p[e];
}

// -------- zero all accumulators --------
__global__ void zero_kernel() {
    int i = blockIdx.x * blockDim.x + threadIdx.x;
    if (i < NN) { g_deg_out[i] = 0.f; g_deg_in[i] = 0.f; }
    if (i < NN * HID) { g_h[i] = 0.f; g_agg1[i] = 0.f; }
    if (i < NN * 8) g_agg2[i] = 0.f;
}

// -------- detect int64 vs int32 edge indices --------
__global__ void detect_kernel(const int* __restrict__ src, const int* __restrict__ dst) {
    int t = threadIdx.x;  // 256 threads
    int v = src[2 * t + 1] | dst[2 * t + 1];
    int any = __syncthreads_or(v != 0);
    if (t == 0) g_is64 = any ? 0 : 1;  // all odd words zero -> int64
}

// -------- degrees --------
__global__ void degree_kernel(const int* __restrict__ src, const int* __restrict__ dst) {
    int e = blockIdx.x * blockDim.x + threadIdx.x;
    if (e >= NE) return;
    int is64 = g_is64;
    atomicAdd(&g_deg_out[edge_at(src, e, is64)], 1.f);
    atomicAdd(&g_deg_in[edge_at(dst, e, is64)], 1.f);
}

// -------- rsqrt norms --------
__global__ void norm_kernel() {
    int i = blockIdx.x * blockDim.x + threadIdx.x;
    if (i >= NN) return;
    g_norm_src[i] = rsqrtf(fmaxf(g_deg_out[i], 1.f));
    g_norm_dst[i] = rsqrtf(fmaxf(g_deg_in[i], 1.f));
}

// -------- layer1 GEMM: g_h[r, 0:16] += norm_src[r] * A[r, k0:k0+500] @ W1[k0:k0+500, :]
// grid = (40 row-blocks, 20 k-splits), 128 threads, 2 rows/thread, f32x2 FMAs.
__global__ __launch_bounds__(128) void gemm1_kernel(const float* __restrict__ A,
                                                    const float* __restrict__ W1) {
    __shared__ float Ws[KCHUNK * HID];  // 32 KB
    int k0 = blockIdx.y * KCHUNK;
    {
        const float4* Wg = (const float4*)(W1 + (size_t)k0 * HID);
        float4* Wsv = (float4*)Ws;
        for (int i = threadIdx.x; i < KCHUNK * HID / 4; i += 128) Wsv[i] = Wg[i];
    }
    __syncthreads();
    int r0 = (blockIdx.x * 128 + threadIdx.x) * 2;
    if (r0 >= NN) return;
    const float* a0p = A + (size_t)r0 * KTOT + k0;
    const float* a1p = a0p + KTOT;

    unsigned long long acc0[8], acc1[8];  // 8 col-pairs per row
#pragma unroll
    for (int j = 0; j < 8; j++) { acc0[j] = 0ull; acc1[j] = 0ull; }

#pragma unroll 2
    for (int k = 0; k < KCHUNK; k += 4) {
        float4 a0 = *(const float4*)(a0p + k);
        float4 a1 = *(const float4*)(a1p + k);
#pragma unroll
        for (int kk = 0; kk < 4; kk++) {
            float av0 = kk == 0 ? a0.x : kk == 1 ? a0.y : kk == 2 ? a0.z : a0.w;
            float av1 = kk == 0 ? a1.x : kk == 1 ? a1.y : kk == 2 ? a1.z : a1.w;
            unsigned long long d0, d1;
            asm("mov.b64 %0, {%1, %1};" : "=l"(d0) : "r"(__float_as_uint(av0)));
            asm("mov.b64 %0, {%1, %1};" : "=l"(d1) : "r"(__float_as_uint(av1)));
            const ulonglong2* wr = (const ulonglong2*)(Ws + (k + kk) * HID);
            ulonglong2 wa = wr[0], wb = wr[1], wc = wr[2], wd = wr[3];
            unsigned long long w[8] = {wa.x, wa.y, wb.x, wb.y, wc.x, wc.y, wd.x, wd.y};
#pragma unroll
            for (int j = 0; j < 8; j++) {
                asm("fma.rn.f32x2 %0, %1, %2, %0;" : "+l"(acc0[j]) : "l"(d0), "l"(w[j]));
                asm("fma.rn.f32x2 %0, %1, %2, %0;" : "+l"(acc1[j]) : "l"(d1), "l"(w[j]));
            }
        }
    }

    float ns0 = g_norm_src[r0], ns1 = g_norm_src[r0 + 1];
#pragma unroll
    for (int j = 0; j < 8; j++) {
        float2 v0 = *(float2*)&acc0[j];
        float2 v1 = *(float2*)&acc1[j];
        atomicAdd(&g_h[r0 * HID + 2 * j],           v0.x * ns0);
        atomicAdd(&g_h[r0 * HID + 2 * j + 1],       v0.y * ns0);
        atomicAdd(&g_h[(r0 + 1) * HID + 2 * j],     v1.x * ns1);
        atomicAdd(&g_h[(r0 + 1) * HID + 2 * j + 1], v1.y * ns1);
    }
}

// -------- edge scatter 1: agg1[dst] += h[src] --------
__global__ void scatter1_kernel(const int* __restrict__ src, const int* __restrict__ dst) {
    int idx = blockIdx.x * blockDim.x + threadIdx.x;
    if (idx >= NE * HID) return;
    int e = idx >> 4, j = idx & 15;
    int is64 = g_is64;
    int s = edge_at(src, e, is64);
    int d = edge_at(dst, e, is64);
    atomicAdd(&g_agg1[d * HID + j], g_h[s * HID + j]);
}

// -------- relu + norm + layer2 GEMM (16x7) --------
__global__ void act_gemm2_kernel(const float* __restrict__ b1, const float* __restrict__ W2) {
    __shared__ float W2s[HID * NL];
    __shared__ float b1s[HID];
    int t = threadIdx.x;
    if (t < HID * NL) W2s[t] = W2[t];
    if (t < HID) b1s[t] = b1[t];
    __syncthreads();
    int i = blockIdx.x * blockDim.x + t;
    if (i >= NN) return;
    float nd = g_norm_dst[i], ns = g_norm_src[i];
    float o[NL];
#pragma unroll
    for (int l = 0; l < NL; l++) o[l] = 0.f;
    const float4* ag = (const float4*)(g_agg1 + i * HID);
#pragma unroll
    for (int q = 0; q < 4; q++) {
        float4 v = ag[q];
        float hv[4] = {v.x, v.y, v.z, v.w};
#pragma unroll
        for (int u = 0; u < 4; u++) {
            int j = q * 4 + u;
            float h1 = fmaxf(hv[u] * nd + b1s[j], 0.f) * ns;
#pragma unroll
            for (int l = 0; l < NL; l++) o[l] += h1 * W2s[j * NL + l];
        }
    }
#pragma unroll
    for (int l = 0; l < NL; l++) g_h2[i * 8 + l] = o[l];
}

// -------- edge scatter 2: agg2[dst] += h2[src] --------
__global__ void scatter2_kernel(const int* __restrict__ src, const int* __restrict__ dst) {
    int idx = blockIdx.x * blockDim.x + threadIdx.x;
    if (idx >= NE * 8) return;
    int e = idx >> 3, j = idx & 7;
    if (j >= NL) return;
    int is64 = g_is64;
    int s = edge_at(src, e, is64);
    int d = edge_at(dst, e, is64);
    atomicAdd(&g_agg2[d * 8 + j], g_h2[s * 8 + j]);
}

// -------- epilogue: out = agg2 * norm_dst + b2 --------
__global__ void final_kernel(const float* __restrict__ b2, float* __restrict__ out) {
    int idx = blockIdx.x * blockDim.x + threadIdx.x;
    if (idx >= NN * NL) return;
    int i = idx / NL, l = idx - i * NL;
    out[idx] = g_agg2[i * 8 + l] * g_norm_dst[i] + __ldg(&b2[l]);
}

extern "C" void kernel_launch(void* const* d_in, const int* in_sizes, int n_in,
                              void* d_out, int out_size) {
    const float* features = (const float*)d_in[0];
    const int*   src      = (const int*)d_in[1];   // int32 or int64 (detected)
    const int*   dst      = (const int*)d_in[2];
    const float* W1       = (const float*)d_in[3];
    const float* b1       = (const float*)d_in[4];
    const float* W2       = (const float*)d_in[5];
    const float* b2       = (const float*)d_in[6];
    float* out = (float*)d_out;

    zero_kernel<<<(NN * HID + 255) / 256, 256>>>();
    detect_kernel<<<1, 256>>>(src, dst);
    degree_kernel<<<(NE + 255) / 256, 256>>>(src, dst);
    norm_kernel<<<(NN + 255) / 256, 256>>>();
    gemm1_kernel<<<dim3((NN + 255) / 256, KTOT / KCHUNK), 128>>>(features, W1);
    scatter1_kernel<<<(NE * HID + 255) / 256, 256>>>(src, dst);
    act_gemm2_kernel<<<(NN + 255) / 256, 256>>>(b1, W2);
    scatter2_kernel<<<(NE * 8 + 255) / 256, 256>>>(src, dst);
    final_kernel<<<(NN * NL + 255) / 256, 256>>>(b2, out);
}